// round 14
// baseline (speedup 1.0000x reference)
#include <cuda_runtime.h>
#include <cuda_fp16.h>
#include <cstdint>

#define NND 50000
#define NE  800000
#define EDIM 64
#define NS  23
#define MDIM 87
#define HH  200
#define RDIM 256
#define NMOLS 2048
#define NB_SCAN 196   // ceil(NND/256)

// ---------------- scratch (device globals; no allocations) ----------------
__device__ float  g_x[NND * EDIM];
__device__ float  g_xall[NND * RDIM];
__device__ float  g_mrbf[NND * 24];
__device__ float  g_mx[NND * EDIM];
__device__ __half g_h1[NND * HH];
__device__ __half g_h2[NND * HH];
// stats layout: [0..23) rbf sum (persistent), [23..87) mx sum (self-clean),
//               [87..110) rbf sumsq (persistent), [110..174) mx sumsq (self-clean),
//               [512..768) ro sum (self-clean), [768..1024) ro sumsq (self-clean)
__device__ float  g_stats[1024];
__device__ float  g_ac[2 * RDIM];
__device__ int    g_tick_mx;
__device__ int    g_tick_ro;
__device__ int    g_tick_scan;
__device__ __half g_wH[482000];         // n-major [NW][KPAD] fp16 weights
// CSR scratch
__device__ int   g_cnt[NND];
__device__ int   g_excl[NND];
__device__ int   g_bsum[256];
__device__ int   g_boff[256];
__device__ int   g_row[NND + 1];
__device__ int   g_pos[NND];
__device__ int   g_esnk_s[NE];
__device__ float g_edist_s[NE];

// wH offsets (halves)
#define WH_UP1 0        // 3 x 200x96
#define WH_UP2 57600    // 3 x 200x208
#define WH_UP3 182400   // 3 x 200x208
#define WH_UP4 307200   // 3 x 64x208
#define WH_RO1 347136   // 200x256
#define WH_RO2 398336   // 200x208
#define WH_RO3 439936   // 200x208

// ---------------- helpers ----------------
__device__ __forceinline__ uint32_t smem_u32(const void* p) {
    uint32_t a;
    asm("{ .reg .u64 t; cvta.to.shared.u64 t, %1; cvt.u32.u64 %0, t; }" : "=r"(a) : "l"(p));
    return a;
}
__device__ __forceinline__ void cp_async16(uint32_t dst, const void* src, int valid) {
    asm volatile("cp.async.cg.shared.global [%0], [%1], 16, %2;"
                 :: "r"(dst), "l"(src), "r"(valid) : "memory");
}
__device__ __forceinline__ void mma_f16(float* d, const uint32_t* a, const uint32_t* b) {
    asm volatile(
        "mma.sync.aligned.m16n8k16.row.col.f32.f16.f16.f32 "
        "{%0,%1,%2,%3}, {%4,%5,%6,%7}, {%8,%9}, {%0,%1,%2,%3};"
        : "+f"(d[0]), "+f"(d[1]), "+f"(d[2]), "+f"(d[3])
        : "r"(a[0]), "r"(a[1]), "r"(a[2]), "r"(a[3]), "r"(b[0]), "r"(b[1]));
}
__device__ __forceinline__ void ldsm_x4(uint32_t* r, uint32_t addr) {
    asm volatile("ldmatrix.sync.aligned.m8n8.x4.shared.b16 {%0,%1,%2,%3}, [%4];"
                 : "=r"(r[0]), "=r"(r[1]), "=r"(r[2]), "=r"(r[3]) : "r"(addr));
}
__device__ __forceinline__ uint32_t pack_h2(float a, float b) {
    __half2 h = __floats2half2_rn(a, b);
    return *(uint32_t*)&h;
}

// ---------------- init / utility ----------------
// zero y + g_cnt + persistent rbf stat slots (everything else is self-cleaning)
__global__ void init_zero(float* __restrict__ y) {
    int i = blockIdx.x * blockDim.x + threadIdx.x;
    if (i < NMOLS) y[i] = 0.f;
    if (i < NND) g_cnt[i] = 0;
    if (blockIdx.x == 0 && threadIdx.x < NS) {
        g_stats[threadIdx.x] = 0.f;
        g_stats[MDIM + threadIdx.x] = 0.f;
    }
}
__global__ void embed_kernel(const int* __restrict__ z, const float* __restrict__ emb) {
    int i = blockIdx.x * blockDim.x + threadIdx.x;
    if (i >= NND * EDIM) return;
    int n = i >> 6, d = i & 63;
    float v = emb[(z[n] << 6) + d];
    g_x[i] = v;
    g_xall[(n << 8) + d] = v;
}

// all 7 weight transposes fused: in [nt][K][NW] float -> wH[off + [nt][NW][KPAD]] half
__global__ void transpose_all(const float* __restrict__ w1, const float* __restrict__ w2,
                              const float* __restrict__ w3, const float* __restrict__ w4,
                              const float* __restrict__ r1, const float* __restrict__ r2,
                              const float* __restrict__ r3, __half* __restrict__ out) {
    int gid = blockIdx.x * blockDim.x + threadIdx.x;
    int stride = gridDim.x * blockDim.x;
    auto doReg = [&](const float* __restrict__ in, int K, int NW, int KPAD, int off, int total) {
        int per = NW * KPAD;
        for (int i = gid; i < total; i += stride) {
            int t = i / per, rem = i - t * per;
            int n = rem / KPAD, k = rem - n * KPAD;
            float v = (k < K) ? in[(size_t)t * K * NW + (size_t)k * NW + n] : 0.f;
            out[off + i] = __float2half(v);
        }
    };
    doReg(w1, MDIM, HH,   96, WH_UP1, 57600);
    doReg(w2, HH,   HH,  208, WH_UP2, 124800);
    doReg(w3, HH,   HH,  208, WH_UP3, 124800);
    doReg(w4, HH,  EDIM, 208, WH_UP4, 39936);
    doReg(r1, RDIM, HH,  256, WH_RO1, 51200);
    doReg(r2, HH,   HH,  208, WH_RO2, 41600);
    doReg(r3, HH,   HH,  208, WH_RO3, 41600);
}

// ---------------- CSR build ----------------
__global__ void csr_count(const int* __restrict__ esrc) {
    int e = blockIdx.x * blockDim.x + threadIdx.x;
    if (e < NE) atomicAdd(&g_cnt[esrc[e]], 1);
}
// local scan; last block also scans the block sums into g_boff (ticket pattern)
__global__ void scan_local() {
    __shared__ int sh[256];
    __shared__ int lastf;
    int i = blockIdx.x * 256 + threadIdx.x;
    int v = (i < NND) ? g_cnt[i] : 0;
    sh[threadIdx.x] = v;
    __syncthreads();
    #pragma unroll
    for (int off = 1; off < 256; off <<= 1) {
        int t = (threadIdx.x >= off) ? sh[threadIdx.x - off] : 0;
        __syncthreads();
        sh[threadIdx.x] += t;
        __syncthreads();
    }
    if (i < NND) g_excl[i] = sh[threadIdx.x] - v;
    if (threadIdx.x == 255) g_bsum[blockIdx.x] = sh[255];
    __syncthreads();
    if (threadIdx.x == 0) {
        __threadfence();
        lastf = (atomicAdd(&g_tick_scan, 1) == (int)gridDim.x - 1);
    }
    __syncthreads();
    if (lastf) {
        int b = (threadIdx.x < NB_SCAN) ? g_bsum[threadIdx.x] : 0;
        sh[threadIdx.x] = b;
        __syncthreads();
        #pragma unroll
        for (int off = 1; off < 256; off <<= 1) {
            int t = (threadIdx.x >= off) ? sh[threadIdx.x - off] : 0;
            __syncthreads();
            sh[threadIdx.x] += t;
            __syncthreads();
        }
        g_boff[threadIdx.x] = sh[threadIdx.x] - b;
        if (threadIdx.x == 0) g_tick_scan = 0;
    }
}
__global__ void scan_add() {
    int i = blockIdx.x * blockDim.x + threadIdx.x;
    if (i < NND) {
        int r = g_excl[i] + g_boff[i >> 8];
        g_row[i] = r;
        g_pos[i] = r;
    }
    if (i == 0) g_row[NND] = NE;
}
__global__ void csr_fill(const int* __restrict__ esrc, const int* __restrict__ esnk,
                         const float* __restrict__ dist) {
    int e = blockIdx.x * blockDim.x + threadIdx.x;
    if (e >= NE) return;
    int p = atomicAdd(&g_pos[esrc[e]], 1);
    g_esnk_s[p] = esnk[e];
    g_edist_s[p] = dist[e];
}

// ---------------- gathers ----------------
__global__ void gather_x() {
    int gt = blockIdx.x * blockDim.x + threadIdx.x;
    int node = gt >> 5, lane = gt & 31;
    if (node >= NND) return;
    int s = g_row[node], e = g_row[node + 1];
    float a0 = 0.f, a1 = 0.f;
    for (int i = s; i < e; i++) {
        int snk = g_esnk_s[i] << 6;
        a0 += g_x[snk + lane];
        a1 += g_x[snk + 32 + lane];
    }
    g_mx[(node << 6) + lane] = a0;
    g_mx[(node << 6) + 32 + lane] = a1;
}
__global__ void gather_rbf() {
    int node = blockIdx.x * blockDim.x + threadIdx.x;
    if (node >= NND) return;
    int s = g_row[node], e = g_row[node + 1];
    float acc[NS];
    #pragma unroll
    for (int f = 0; f < NS; f++) acc[f] = 0.f;
    for (int i = s; i < e; i++) {
        float t = g_edist_s[i] - 0.8f;
        float v = __expf(-t * t);
        float u = __expf(0.2f * t);
        float r = u * 0.99004983f;
        acc[0] += v;
        #pragma unroll
        for (int f = 1; f < NS; f++) {
            v *= r;
            acc[f] += v;
            r *= 0.98019867f;
        }
    }
    #pragma unroll
    for (int f = 0; f < NS; f++) g_mrbf[node * 24 + f] = acc[f];
}

// ---------------- batchnorm stats (self-cleaning, fused finalize) ----------------
__global__ void stats_rbf() {
    __shared__ float ss[24], sq[24];
    if (threadIdx.x < 24) { ss[threadIdx.x] = 0.f; sq[threadIdx.x] = 0.f; }
    __syncthreads();
    int stride = gridDim.x * blockDim.x;
    for (int idx = blockIdx.x * blockDim.x + threadIdx.x; idx < NND * 24; idx += stride) {
        int c = idx % 24;
        if (c < NS) {
            float v = g_mrbf[idx];
            atomicAdd(&ss[c], v);
            atomicAdd(&sq[c], v * v);
        }
    }
    __syncthreads();
    if (threadIdx.x < NS) {
        atomicAdd(&g_stats[threadIdx.x], ss[threadIdx.x]);
        atomicAdd(&g_stats[MDIM + threadIdx.x], sq[threadIdx.x]);
    }
}

// mx stats over g_mx; last block computes full MDIM g_ac (rbf part persistent),
// then zeroes the mx slots + tick for the next pass / graph replay.
__global__ void stats_mx_fin(const float* __restrict__ bng, const float* __restrict__ bnb) {
    int tid = threadIdx.x;
    float s = 0.f, q = 0.f;
    int stride = gridDim.x * 256;
    for (int idx = blockIdx.x * 256 + tid; idx < NND * EDIM; idx += stride) {
        float v = g_mx[idx];
        s += v; q += v * v;
    }
    __shared__ float sh[512];
    __shared__ int lastf;
    sh[tid] = s; sh[256 + tid] = q;
    __syncthreads();
    if (tid < 64) {
        float S = 0.f, Q = 0.f;
        #pragma unroll
        for (int j = tid; j < 256; j += 64) { S += sh[j]; Q += sh[256 + j]; }
        atomicAdd(&g_stats[NS + tid], S);
        atomicAdd(&g_stats[MDIM + NS + tid], Q);
        __threadfence();
    }
    __syncthreads();
    if (tid == 0) lastf = (atomicAdd(&g_tick_mx, 1) == (int)gridDim.x - 1);
    __syncthreads();
    if (lastf) {
        if (tid < MDIM) {
            const float inv = 1.f / (float)NND;
            float mean = g_stats[tid] * inv;
            float var = fmaxf(g_stats[MDIM + tid] * inv - mean * mean, 0.f);
            float a = bng[tid] * rsqrtf(var + 1e-5f);
            g_ac[tid] = a;
            g_ac[MDIM + tid] = bnb[tid] - mean * a;
        }
        __syncthreads();
        if (tid < 64) { g_stats[NS + tid] = 0.f; g_stats[MDIM + NS + tid] = 0.f; }
        if (tid == 0) g_tick_mx = 0;
    }
}

// readout stats over g_xall (RDIM cols); last block computes RDIM g_ac and self-cleans.
__global__ void stats_ro_fin(const float* __restrict__ bng, const float* __restrict__ bnb) {
    int tid = threadIdx.x;
    float s = 0.f, q = 0.f;
    int stride = gridDim.x * 256;
    for (int idx = blockIdx.x * 256 + tid; idx < NND * RDIM; idx += stride) {
        float v = g_xall[idx];
        s += v; q += v * v;
    }
    __shared__ int lastf;
    atomicAdd(&g_stats[512 + tid], s);
    atomicAdd(&g_stats[768 + tid], q);
    __threadfence();
    __syncthreads();
    if (tid == 0) lastf = (atomicAdd(&g_tick_ro, 1) == (int)gridDim.x - 1);
    __syncthreads();
    if (lastf) {
        const float inv = 1.f / (float)NND;
        float mean = g_stats[512 + tid] * inv;
        float var = fmaxf(g_stats[768 + tid] * inv - mean * mean, 0.f);
        float a = bng[tid] * rsqrtf(var + 1e-5f);
        g_ac[tid] = a;
        g_ac[RDIM + tid] = bnb[tid] - mean * a;
        g_stats[512 + tid] = 0.f;
        g_stats[768 + tid] = 0.f;
        if (tid == 0) g_tick_ro = 0;
    }
}

// ---------------- fp16 m16n8k16 double-buffered GEMM (ldmatrix fragments) ------
// BN = WNT*16 (WNT=4 -> 64 wide, WNT=8 -> 128 wide). 8 warps as 4(m) x 2(n).
// D[128 x NN] = epi(A' @ WH^T + bias). WH: [NW][KPAD] n-major half.
// Paths: SPLITA (mrbf+mx, BN fold), BNIN (fp32 A, BN fold), else cp.async half A.
// RESID: g_x += 0.1*D (fp32) + g_xall slice.
// FINAL: relu then dot with w4, atomicAdd into y[mol[row]] (b4 from y-block 0 only).
template <int KTOT, int NCH, int NN, int NW, int WNT, bool RELU, bool BNIN, bool RESID,
          bool SPLITA, bool FINAL>
__global__ __launch_bounds__(256, 2)
void gemm_f16(const void* __restrict__ Ain, const __half* __restrict__ WH,
              const float* __restrict__ bias, __half* __restrict__ out, int xall_off,
              const float* __restrict__ w4, const float* __restrict__ b4,
              const int* __restrict__ mol, float* __restrict__ y) {
    constexpr int KPAD = NCH * 16;
    constexpr int BN = WNT * 16;
    constexpr int AW = 128 * 12;   // A stage words ([row][8 half2 words], stride 12)
    constexpr int BW = BN * 12;    // B stage words
    __shared__ __align__(16) uint32_t sbuf[2][AW + BW];

    int tid = threadIdx.x, lane = tid & 31, wid = tid >> 5;
    int warp_m = wid & 3, warp_n = wid >> 2;
    int g = lane >> 2, tig = lane & 3;
    int l8 = lane & 7, lq = lane >> 3;
    int bm = blockIdx.x * 128, bn = blockIdx.y * BN;
    uint32_t sbase = smem_u32(sbuf);

    float acc[2][WNT][4] = {};

#define STAGE(cc, bb) do { \
    int k0_ = (cc) * 16; \
    uint32_t* As_ = sbuf[bb]; \
    uint32_t aAdr_ = sbase + (uint32_t)(bb) * (AW + BW) * 4; \
    uint32_t bAdr_ = aAdr_ + AW * 4; \
    if (SPLITA) { \
        _Pragma("unroll") \
        for (int j = 0; j < 4; j++) { \
            int idx = tid + j * 256; \
            int row = idx >> 3, w = idx & 7; \
            int gr = bm + row, gk = k0_ + 2 * w; \
            float v0 = 0.f, v1 = 0.f; \
            if (gr < NND) { \
                if (gk < KTOT) { \
                    v0 = (gk < NS) ? g_mrbf[gr * 24 + gk] : g_mx[gr * 64 + gk - NS]; \
                    v0 = fmaf(v0, g_ac[gk], g_ac[KTOT + gk]); \
                } \
                if (gk + 1 < KTOT) { \
                    v1 = (gk + 1 < NS) ? g_mrbf[gr * 24 + gk + 1] : g_mx[gr * 64 + gk + 1 - NS]; \
                    v1 = fmaf(v1, g_ac[gk + 1], g_ac[KTOT + gk + 1]); \
                } \
            } \
            As_[row * 12 + w] = pack_h2(v0, v1); \
        } \
    } else if (BNIN) { \
        const float* Af = (const float*)Ain; \
        _Pragma("unroll") \
        for (int j = 0; j < 2; j++) { \
            int idx = tid + j * 256; \
            int row = idx >> 2, wq = idx & 3; \
            int gr = bm + row, gk = k0_ + wq * 4; \
            float4 v = {0.f, 0.f, 0.f, 0.f}; \
            if (gr < NND && gk + 4 <= KTOT) v = *(const float4*)(Af + (size_t)gr * KTOT + gk); \
            float f0 = (gr < NND) ? fmaf(v.x, g_ac[gk + 0], g_ac[KTOT + gk + 0]) : 0.f; \
            float f1 = (gr < NND) ? fmaf(v.y, g_ac[gk + 1], g_ac[KTOT + gk + 1]) : 0.f; \
            float f2 = (gr < NND) ? fmaf(v.z, g_ac[gk + 2], g_ac[KTOT + gk + 2]) : 0.f; \
            float f3 = (gr < NND) ? fmaf(v.w, g_ac[gk + 3], g_ac[KTOT + gk + 3]) : 0.f; \
            As_[row * 12 + wq * 2 + 0] = pack_h2(f0, f1); \
            As_[row * 12 + wq * 2 + 1] = pack_h2(f2, f3); \
        } \
    } else { \
        const __half* Ah = (const __half*)Ain; \
        int row = tid >> 1, kq = tid & 1; \
        int gr = bm + row, gk = k0_ + kq * 8; \
        int vld = (gr < NND && gk + 8 <= KTOT) ? 16 : 0; \
        const __half* src = vld ? (Ah + (size_t)gr * KTOT + gk) : Ah; \
        cp_async16(aAdr_ + (uint32_t)(row * 12 + kq * 4) * 4, src, vld); \
    } \
    _Pragma("unroll") \
    for (int j = tid; j < BN * 2; j += 256) { \
        int row = j >> 1, kq = j & 1; \
        int gn = bn + row; \
        int vld = (gn < NW) ? 16 : 0; \
        const __half* src = vld ? (WH + (size_t)gn * KPAD + k0_ + kq * 8) : WH; \
        cp_async16(bAdr_ + (uint32_t)(row * 12 + kq * 4) * 4, src, vld); \
    } \
    asm volatile("cp.async.commit_group;" ::: "memory"); \
} while (0)

    STAGE(0, 0);
    for (int c = 0; c < NCH; c++) {
        if (c + 1 < NCH) {
            STAGE(c + 1, (c + 1) & 1);
            asm volatile("cp.async.wait_group 1;" ::: "memory");
        } else {
            asm volatile("cp.async.wait_group 0;" ::: "memory");
        }
        __syncthreads();
        uint32_t aSm = sbase + (uint32_t)(c & 1) * (AW + BW) * 4;
        uint32_t bSm = aSm + AW * 4;
        uint32_t af[2][4], bf[WNT][2];
        // A fragments: one ldmatrix.x4 per 16-row tile
        #pragma unroll
        for (int mt = 0; mt < 2; mt++) {
            int row = warp_m * 32 + mt * 16 + l8 + ((lq & 1) << 3);
            ldsm_x4(af[mt], aSm + (uint32_t)(row * 12 + ((lq >> 1) << 2)) * 4);
        }
        // B fragments: one ldmatrix.x4 covers two 8-col groups (both k-halves)
        #pragma unroll
        for (int j = 0; j < WNT / 2; j++) {
            int col = warp_n * (WNT * 8) + (2 * j + (lq >> 1)) * 8 + l8;
            uint32_t r4[4];
            ldsm_x4(r4, bSm + (uint32_t)(col * 12 + ((lq & 1) << 2)) * 4);
            bf[2 * j][0] = r4[0]; bf[2 * j][1] = r4[1];
            bf[2 * j + 1][0] = r4[2]; bf[2 * j + 1][1] = r4[3];
        }
        #pragma unroll
        for (int mt = 0; mt < 2; mt++)
            #pragma unroll
            for (int nt = 0; nt < WNT; nt++)
                mma_f16(acc[mt][nt], af[mt], bf[nt]);
        __syncthreads();
    }
#undef STAGE

    // ---- epilogue ----
    if (FINAL) {
        #pragma unroll
        for (int mt = 0; mt < 2; mt++) {
            #pragma unroll
            for (int h = 0; h < 2; h++) {
                int r = bm + warp_m * 32 + mt * 16 + g + h * 8;
                float part = 0.f;
                #pragma unroll
                for (int nt = 0; nt < WNT; nt++) {
                    int c0 = bn + warp_n * (WNT * 8) + nt * 8 + tig * 2;
                    if (c0 < NN) {
                        float v0 = fmaxf(acc[mt][nt][h * 2 + 0] + __ldg(bias + c0), 0.f);
                        float v1 = fmaxf(acc[mt][nt][h * 2 + 1] + __ldg(bias + c0 + 1), 0.f);
                        part += v0 * __ldg(w4 + c0) + v1 * __ldg(w4 + c0 + 1);
                    }
                }
                part += __shfl_xor_sync(0xffffffffu, part, 1);
                part += __shfl_xor_sync(0xffffffffu, part, 2);
                if (tig == 0 && r < NND) {
                    if (blockIdx.y == 0) part += __ldg(b4);
                    atomicAdd(&y[__ldg(mol + r)], part);
                }
            }
        }
        return;
    }
    #pragma unroll
    for (int mt = 0; mt < 2; mt++) {
        #pragma unroll
        for (int nt = 0; nt < WNT; nt++) {
            int r0 = bm + warp_m * 32 + mt * 16 + g;
            int c0 = bn + warp_n * (WNT * 8) + nt * 8 + tig * 2;
            float* d = acc[mt][nt];
            #pragma unroll
            for (int h = 0; h < 2; h++) {
                int r = r0 + h * 8;
                if (r < NND && c0 < NN) {
                    float v0 = d[h * 2 + 0] + __ldg(bias + c0);
                    float v1 = d[h * 2 + 1] + __ldg(bias + c0 + 1);
                    if (RELU) { v0 = fmaxf(v0, 0.f); v1 = fmaxf(v1, 0.f); }
                    if (RESID) {
                        float2 xo = *(float2*)&g_x[r * EDIM + c0];
                        float2 xn = {xo.x + 0.1f * v0, xo.y + 0.1f * v1};
                        *(float2*)&g_x[r * EDIM + c0] = xn;
                        *(float2*)&g_xall[r * RDIM + xall_off + c0] = xn;
                    } else {
                        __half2 hv = __floats2half2_rn(v0, v1);
                        *(__half2*)&out[(size_t)r * NN + c0] = hv;
                    }
                }
            }
        }
    }
}

// ---------------- launch ----------------
extern "C" void kernel_launch(void* const* d_in, const int* in_sizes, int n_in,
                              void* d_out, int out_size) {
    const int*   z     = (const int*)d_in[0];
    const int*   eidx  = (const int*)d_in[1];
    const float* dist  = (const float*)d_in[2];
    const int*   mol   = (const int*)d_in[3];
    const float* emb   = (const float*)d_in[4];
    const float* up_bn_g = (const float*)d_in[5];
    const float* up_bn_b = (const float*)d_in[6];
    const float* up_w1 = (const float*)d_in[7];
    const float* up_b1 = (const float*)d_in[8];
    const float* up_w2 = (const float*)d_in[9];
    const float* up_b2 = (const float*)d_in[10];
    const float* up_w3 = (const float*)d_in[11];
    const float* up_b3 = (const float*)d_in[12];
    const float* up_w4 = (const float*)d_in[13];
    const float* up_b4 = (const float*)d_in[14];
    const float* ro_bn_g = (const float*)d_in[15];
    const float* ro_bn_b = (const float*)d_in[16];
    const float* ro_w1 = (const float*)d_in[17];
    const float* ro_b1 = (const float*)d_in[18];
    const float* ro_w2 = (const float*)d_in[19];
    const float* ro_b2 = (const float*)d_in[20];
    const float* ro_w3 = (const float*)d_in[21];
    const float* ro_b3 = (const float*)d_in[22];
    const float* ro_w4 = (const float*)d_in[23];
    const float* ro_b4 = (const float*)d_in[24];
    float* y = (float*)d_out;

    float *pxall;
    __half *ph1, *ph2, *pwH;
    cudaGetSymbolAddress((void**)&ph1, g_h1);
    cudaGetSymbolAddress((void**)&ph2, g_h2);
    cudaGetSymbolAddress((void**)&pxall, g_xall);
    cudaGetSymbolAddress((void**)&pwH, g_wH);

    init_zero<<<NB_SCAN, 256>>>(y);
    embed_kernel<<<(NND * EDIM + 255) / 256, 256>>>(z, emb);

    // all weight transposes -> n-major fp16 (one kernel)
    transpose_all<<<232, 256>>>(up_w1, up_w2, up_w3, up_w4, ro_w1, ro_w2, ro_w3, pwH);

    // CSR build
    csr_count<<<(NE + 255) / 256, 256>>>(eidx);
    scan_local<<<NB_SCAN, 256>>>();
    scan_add<<<(NND + 255) / 256, 256>>>();
    csr_fill<<<(NE + 255) / 256, 256>>>(eidx, eidx + NE, dist);

    // one-time rbf gather + pass-invariant stats (persistent slots)
    gather_rbf<<<(NND + 255) / 256, 256>>>();
    stats_rbf<<<296, 256>>>();

    const int GB = (NND + 127) / 128;   // 391
    dim3 gH(GB, 2), gE(GB, 1);          // 128-wide tiles for N=200; 64-wide for N=64

    for (int t = 0; t < 3; t++) {
        gather_x<<<(NND * 32 + 255) / 256, 256>>>();
        stats_mx_fin<<<296, 256>>>(up_bn_g + t * MDIM, up_bn_b + t * MDIM);
        gemm_f16<MDIM, 6, HH, HH, 8, true, false, false, true, false><<<gH, 256>>>(
            nullptr, pwH + WH_UP1 + t * HH * 96, up_b1 + t * HH, ph1, 0,
            nullptr, nullptr, nullptr, nullptr);
        gemm_f16<HH, 13, HH, HH, 8, true, false, false, false, false><<<gH, 256>>>(
            ph1, pwH + WH_UP2 + t * HH * 208, up_b2 + t * HH, ph2, 0,
            nullptr, nullptr, nullptr, nullptr);
        gemm_f16<HH, 13, HH, HH, 8, true, false, false, false, false><<<gH, 256>>>(
            ph2, pwH + WH_UP3 + t * HH * 208, up_b3 + t * HH, ph1, 0,
            nullptr, nullptr, nullptr, nullptr);
        gemm_f16<HH, 13, EDIM, EDIM, 4, false, false, true, false, false><<<gE, 256>>>(
            ph1, pwH + WH_UP4 + t * EDIM * 208, up_b4 + t * EDIM, nullptr, EDIM * (t + 1),
            nullptr, nullptr, nullptr, nullptr);
    }

    stats_ro_fin<<<296, 256>>>(ro_bn_g, ro_bn_b);
    gemm_f16<RDIM, 16, HH, HH, 8, true, true, false, false, false><<<gH, 256>>>(
        pxall, pwH + WH_RO1, ro_b1, ph1, 0, nullptr, nullptr, nullptr, nullptr);
    gemm_f16<HH, 13, HH, HH, 8, true, false, false, false, false><<<gH, 256>>>(
        ph1, pwH + WH_RO2, ro_b2, ph2, 0, nullptr, nullptr, nullptr, nullptr);
    // final layer: relu(h2 @ w3 + b3) fused with (· w4 + b4) and molecule scatter
    gemm_f16<HH, 13, HH, HH, 8, true, false, false, false, true><<<gH, 256>>>(
        ph2, pwH + WH_RO3, ro_b3, nullptr, 0, ro_w4, ro_b4, mol, y);
}

// round 16
// speedup vs baseline: 1.3891x; 1.3891x over previous
#include <cuda_runtime.h>
#include <cuda_fp16.h>
#include <cstdint>

#define NND 50000
#define NE  800000
#define EDIM 64
#define NS  23
#define MDIM 87
#define HH  200
#define RDIM 256
#define NMOLS 2048
#define NB_SCAN 196   // ceil(NND/256)

// ---------------- scratch (device globals; no allocations) ----------------
__device__ float  g_x[NND * EDIM];
__device__ float  g_xall[NND * RDIM];
__device__ float  g_mrbf[NND * 24];
__device__ float  g_mx[NND * EDIM];
__device__ __half g_h1[NND * HH];
__device__ __half g_h2[NND * HH];
// stats layout: [0..23) rbf sum (persistent), [23..87) mx sum (self-clean),
//               [87..110) rbf sumsq (persistent), [110..174) mx sumsq (self-clean),
//               [512..768) ro sum (self-clean), [768..1024) ro sumsq (self-clean)
__device__ float  g_stats[1024];
__device__ float  g_ac[2 * RDIM];
__device__ int    g_tick_mx;
__device__ int    g_tick_ro;
__device__ int    g_tick_scan;
__device__ __half g_wH[482000];         // n-major [NW][KPAD] fp16 weights
// CSR scratch
__device__ int   g_cnt[NND];
__device__ int   g_excl[NND];
__device__ int   g_bsum[256];
__device__ int   g_boff[256];
__device__ int   g_row[NND + 1];
__device__ int   g_pos[NND];
__device__ int   g_esnk_s[NE];
__device__ float g_edist_s[NE];

// wH offsets (halves)
#define WH_UP1 0        // 3 x 200x96
#define WH_UP2 57600    // 3 x 200x208
#define WH_UP3 182400   // 3 x 200x208
#define WH_UP4 307200   // 3 x 64x208
#define WH_RO1 347136   // 200x256
#define WH_RO2 398336   // 200x208
#define WH_RO3 439936   // 200x208

// ---------------- helpers ----------------
__device__ __forceinline__ uint32_t smem_u32(const void* p) {
    uint32_t a;
    asm("{ .reg .u64 t; cvta.to.shared.u64 t, %1; cvt.u32.u64 %0, t; }" : "=r"(a) : "l"(p));
    return a;
}
__device__ __forceinline__ void cp_async16(uint32_t dst, const void* src, int valid) {
    asm volatile("cp.async.cg.shared.global [%0], [%1], 16, %2;"
                 :: "r"(dst), "l"(src), "r"(valid) : "memory");
}
__device__ __forceinline__ void mma_f16(float* d, const uint32_t* a, const uint32_t* b) {
    asm volatile(
        "mma.sync.aligned.m16n8k16.row.col.f32.f16.f16.f32 "
        "{%0,%1,%2,%3}, {%4,%5,%6,%7}, {%8,%9}, {%0,%1,%2,%3};"
        : "+f"(d[0]), "+f"(d[1]), "+f"(d[2]), "+f"(d[3])
        : "r"(a[0]), "r"(a[1]), "r"(a[2]), "r"(a[3]), "r"(b[0]), "r"(b[1]));
}
__device__ __forceinline__ uint32_t pack_h2(float a, float b) {
    __half2 h = __floats2half2_rn(a, b);
    return *(uint32_t*)&h;
}

// ---------------- init / utility ----------------
// zero y + g_cnt + persistent rbf stat slots (everything else is self-cleaning)
__global__ void init_zero(float* __restrict__ y) {
    int i = blockIdx.x * blockDim.x + threadIdx.x;
    if (i < NMOLS) y[i] = 0.f;
    if (i < NND) g_cnt[i] = 0;
    if (blockIdx.x == 0 && threadIdx.x < NS) {
        g_stats[threadIdx.x] = 0.f;
        g_stats[MDIM + threadIdx.x] = 0.f;
    }
}
__global__ void embed_kernel(const int* __restrict__ z, const float* __restrict__ emb) {
    int i = blockIdx.x * blockDim.x + threadIdx.x;
    if (i >= NND * EDIM) return;
    int n = i >> 6, d = i & 63;
    float v = emb[(z[n] << 6) + d];
    g_x[i] = v;
    g_xall[(n << 8) + d] = v;
}

// all 7 weight transposes fused: in [nt][K][NW] float -> wH[off + [nt][NW][KPAD]] half
__global__ void transpose_all(const float* __restrict__ w1, const float* __restrict__ w2,
                              const float* __restrict__ w3, const float* __restrict__ w4,
                              const float* __restrict__ r1, const float* __restrict__ r2,
                              const float* __restrict__ r3, __half* __restrict__ out) {
    int gid = blockIdx.x * blockDim.x + threadIdx.x;
    int stride = gridDim.x * blockDim.x;
    auto doReg = [&](const float* __restrict__ in, int K, int NW, int KPAD, int off, int total) {
        int per = NW * KPAD;
        for (int i = gid; i < total; i += stride) {
            int t = i / per, rem = i - t * per;
            int n = rem / KPAD, k = rem - n * KPAD;
            float v = (k < K) ? in[(size_t)t * K * NW + (size_t)k * NW + n] : 0.f;
            out[off + i] = __float2half(v);
        }
    };
    doReg(w1, MDIM, HH,   96, WH_UP1, 57600);
    doReg(w2, HH,   HH,  208, WH_UP2, 124800);
    doReg(w3, HH,   HH,  208, WH_UP3, 124800);
    doReg(w4, HH,  EDIM, 208, WH_UP4, 39936);
    doReg(r1, RDIM, HH,  256, WH_RO1, 51200);
    doReg(r2, HH,   HH,  208, WH_RO2, 41600);
    doReg(r3, HH,   HH,  208, WH_RO3, 41600);
}

// ---------------- CSR build ----------------
__global__ void csr_count(const int* __restrict__ esrc) {
    int e = blockIdx.x * blockDim.x + threadIdx.x;
    if (e < NE) atomicAdd(&g_cnt[esrc[e]], 1);
}
// local scan; last block also scans the block sums into g_boff (ticket pattern)
__global__ void scan_local() {
    __shared__ int sh[256];
    __shared__ int lastf;
    int i = blockIdx.x * 256 + threadIdx.x;
    int v = (i < NND) ? g_cnt[i] : 0;
    sh[threadIdx.x] = v;
    __syncthreads();
    #pragma unroll
    for (int off = 1; off < 256; off <<= 1) {
        int t = (threadIdx.x >= off) ? sh[threadIdx.x - off] : 0;
        __syncthreads();
        sh[threadIdx.x] += t;
        __syncthreads();
    }
    if (i < NND) g_excl[i] = sh[threadIdx.x] - v;
    if (threadIdx.x == 255) g_bsum[blockIdx.x] = sh[255];
    __syncthreads();
    if (threadIdx.x == 0) {
        __threadfence();
        lastf = (atomicAdd(&g_tick_scan, 1) == (int)gridDim.x - 1);
    }
    __syncthreads();
    if (lastf) {
        int b = (threadIdx.x < NB_SCAN) ? g_bsum[threadIdx.x] : 0;
        sh[threadIdx.x] = b;
        __syncthreads();
        #pragma unroll
        for (int off = 1; off < 256; off <<= 1) {
            int t = (threadIdx.x >= off) ? sh[threadIdx.x - off] : 0;
            __syncthreads();
            sh[threadIdx.x] += t;
            __syncthreads();
        }
        g_boff[threadIdx.x] = sh[threadIdx.x] - b;
        if (threadIdx.x == 0) g_tick_scan = 0;
    }
}
__global__ void scan_add() {
    int i = blockIdx.x * blockDim.x + threadIdx.x;
    if (i < NND) {
        int r = g_excl[i] + g_boff[i >> 8];
        g_row[i] = r;
        g_pos[i] = r;
    }
    if (i == 0) g_row[NND] = NE;
}
__global__ void csr_fill(const int* __restrict__ esrc, const int* __restrict__ esnk,
                         const float* __restrict__ dist) {
    int e = blockIdx.x * blockDim.x + threadIdx.x;
    if (e >= NE) return;
    int p = atomicAdd(&g_pos[esrc[e]], 1);
    g_esnk_s[p] = esnk[e];
    g_edist_s[p] = dist[e];
}

// ---------------- gathers ----------------
__global__ void gather_x() {
    int gt = blockIdx.x * blockDim.x + threadIdx.x;
    int node = gt >> 5, lane = gt & 31;
    if (node >= NND) return;
    int s = g_row[node], e = g_row[node + 1];
    float a0 = 0.f, a1 = 0.f;
    for (int i = s; i < e; i++) {
        int snk = g_esnk_s[i] << 6;
        a0 += g_x[snk + lane];
        a1 += g_x[snk + 32 + lane];
    }
    g_mx[(node << 6) + lane] = a0;
    g_mx[(node << 6) + 32 + lane] = a1;
}
__global__ void gather_rbf() {
    int node = blockIdx.x * blockDim.x + threadIdx.x;
    if (node >= NND) return;
    int s = g_row[node], e = g_row[node + 1];
    float acc[NS];
    #pragma unroll
    for (int f = 0; f < NS; f++) acc[f] = 0.f;
    for (int i = s; i < e; i++) {
        float t = g_edist_s[i] - 0.8f;
        float v = __expf(-t * t);
        float u = __expf(0.2f * t);
        float r = u * 0.99004983f;
        acc[0] += v;
        #pragma unroll
        for (int f = 1; f < NS; f++) {
            v *= r;
            acc[f] += v;
            r *= 0.98019867f;
        }
    }
    #pragma unroll
    for (int f = 0; f < NS; f++) g_mrbf[node * 24 + f] = acc[f];
}

// ---------------- batchnorm stats (self-cleaning, fused finalize) ----------------
__global__ void stats_rbf() {
    __shared__ float ss[24], sq[24];
    if (threadIdx.x < 24) { ss[threadIdx.x] = 0.f; sq[threadIdx.x] = 0.f; }
    __syncthreads();
    int stride = gridDim.x * blockDim.x;
    for (int idx = blockIdx.x * blockDim.x + threadIdx.x; idx < NND * 24; idx += stride) {
        int c = idx % 24;
        if (c < NS) {
            float v = g_mrbf[idx];
            atomicAdd(&ss[c], v);
            atomicAdd(&sq[c], v * v);
        }
    }
    __syncthreads();
    if (threadIdx.x < NS) {
        atomicAdd(&g_stats[threadIdx.x], ss[threadIdx.x]);
        atomicAdd(&g_stats[MDIM + threadIdx.x], sq[threadIdx.x]);
    }
}

// mx stats over g_mx; last block computes full MDIM g_ac (rbf part persistent),
// then zeroes the mx slots + tick for the next pass / graph replay.
__global__ void stats_mx_fin(const float* __restrict__ bng, const float* __restrict__ bnb) {
    int tid = threadIdx.x;
    float s = 0.f, q = 0.f;
    int stride = gridDim.x * 256;
    for (int idx = blockIdx.x * 256 + tid; idx < NND * EDIM; idx += stride) {
        float v = g_mx[idx];
        s += v; q += v * v;
    }
    __shared__ float sh[512];
    __shared__ int lastf;
    sh[tid] = s; sh[256 + tid] = q;
    __syncthreads();
    if (tid < 64) {
        float S = 0.f, Q = 0.f;
        #pragma unroll
        for (int j = tid; j < 256; j += 64) { S += sh[j]; Q += sh[256 + j]; }
        atomicAdd(&g_stats[NS + tid], S);
        atomicAdd(&g_stats[MDIM + NS + tid], Q);
        __threadfence();
    }
    __syncthreads();
    if (tid == 0) lastf = (atomicAdd(&g_tick_mx, 1) == (int)gridDim.x - 1);
    __syncthreads();
    if (lastf) {
        if (tid < MDIM) {
            const float inv = 1.f / (float)NND;
            float mean = g_stats[tid] * inv;
            float var = fmaxf(g_stats[MDIM + tid] * inv - mean * mean, 0.f);
            float a = bng[tid] * rsqrtf(var + 1e-5f);
            g_ac[tid] = a;
            g_ac[MDIM + tid] = bnb[tid] - mean * a;
        }
        __syncthreads();
        if (tid < 64) { g_stats[NS + tid] = 0.f; g_stats[MDIM + NS + tid] = 0.f; }
        if (tid == 0) g_tick_mx = 0;
    }
}

// readout stats over g_xall (RDIM cols); last block computes RDIM g_ac and self-cleans.
__global__ void stats_ro_fin(const float* __restrict__ bng, const float* __restrict__ bnb) {
    int tid = threadIdx.x;
    float s = 0.f, q = 0.f;
    int stride = gridDim.x * 256;
    for (int idx = blockIdx.x * 256 + tid; idx < NND * RDIM; idx += stride) {
        float v = g_xall[idx];
        s += v; q += v * v;
    }
    __shared__ int lastf;
    atomicAdd(&g_stats[512 + tid], s);
    atomicAdd(&g_stats[768 + tid], q);
    __threadfence();
    __syncthreads();
    if (tid == 0) lastf = (atomicAdd(&g_tick_ro, 1) == (int)gridDim.x - 1);
    __syncthreads();
    if (lastf) {
        const float inv = 1.f / (float)NND;
        float mean = g_stats[512 + tid] * inv;
        float var = fmaxf(g_stats[768 + tid] * inv - mean * mean, 0.f);
        float a = bng[tid] * rsqrtf(var + 1e-5f);
        g_ac[tid] = a;
        g_ac[RDIM + tid] = bnb[tid] - mean * a;
        g_stats[512 + tid] = 0.f;
        g_stats[768 + tid] = 0.f;
        if (tid == 0) g_tick_ro = 0;
    }
}

// ---------------- fp16 m16n8k16 double-buffered GEMM (proven scalar-LDS form) --
// BN = WNT*16 (WNT=4 -> 64 wide, WNT=8 -> 128 wide). 8 warps as 4(m) x 2(n).
// D[128 x NN] = epi(A' @ WH^T + bias). WH: [NW][KPAD] n-major half.
// Paths: SPLITA (mrbf+mx, BN fold), BNIN (fp32 A, BN fold), else cp.async half A.
// RESID: g_x += 0.1*D (fp32) + g_xall slice.
// FINAL: relu then dot with w4, atomicAdd into y[mol[row]] (b4 from y-block 0 only).
template <int KTOT, int NCH, int NN, int NW, int WNT, bool RELU, bool BNIN, bool RESID,
          bool SPLITA, bool FINAL>
__global__ __launch_bounds__(256, 2)
void gemm_f16(const void* __restrict__ Ain, const __half* __restrict__ WH,
              const float* __restrict__ bias, __half* __restrict__ out, int xall_off,
              const float* __restrict__ w4, const float* __restrict__ b4,
              const int* __restrict__ mol, float* __restrict__ y) {
    constexpr int KPAD = NCH * 16;
    constexpr int BN = WNT * 16;
    constexpr int AW = 128 * 12;   // A stage words ([row][8 half2 words], stride 12)
    constexpr int BW = BN * 12;    // B stage words
    __shared__ __align__(16) uint32_t sbuf[2][AW + BW];

    int tid = threadIdx.x, lane = tid & 31, wid = tid >> 5;
    int warp_m = wid & 3, warp_n = wid >> 2;
    int g = lane >> 2, tig = lane & 3;
    int bm = blockIdx.x * 128, bn = blockIdx.y * BN;
    uint32_t sbase = smem_u32(sbuf);

    float acc[2][WNT][4] = {};

#define STAGE(cc, bb) do { \
    int k0_ = (cc) * 16; \
    uint32_t* As_ = sbuf[bb]; \
    uint32_t aAdr_ = sbase + (uint32_t)(bb) * (AW + BW) * 4; \
    uint32_t bAdr_ = aAdr_ + AW * 4; \
    if (SPLITA) { \
        _Pragma("unroll") \
        for (int j = 0; j < 4; j++) { \
            int idx = tid + j * 256; \
            int row = idx >> 3, w = idx & 7; \
            int gr = bm + row, gk = k0_ + 2 * w; \
            float v0 = 0.f, v1 = 0.f; \
            if (gr < NND) { \
                if (gk < KTOT) { \
                    v0 = (gk < NS) ? g_mrbf[gr * 24 + gk] : g_mx[gr * 64 + gk - NS]; \
                    v0 = fmaf(v0, g_ac[gk], g_ac[KTOT + gk]); \
                } \
                if (gk + 1 < KTOT) { \
                    v1 = (gk + 1 < NS) ? g_mrbf[gr * 24 + gk + 1] : g_mx[gr * 64 + gk + 1 - NS]; \
                    v1 = fmaf(v1, g_ac[gk + 1], g_ac[KTOT + gk + 1]); \
                } \
            } \
            As_[row * 12 + w] = pack_h2(v0, v1); \
        } \
    } else if (BNIN) { \
        const float* Af = (const float*)Ain; \
        _Pragma("unroll") \
        for (int j = 0; j < 2; j++) { \
            int idx = tid + j * 256; \
            int row = idx >> 2, wq = idx & 3; \
            int gr = bm + row, gk = k0_ + wq * 4; \
            float4 v = {0.f, 0.f, 0.f, 0.f}; \
            if (gr < NND && gk + 4 <= KTOT) v = *(const float4*)(Af + (size_t)gr * KTOT + gk); \
            float f0 = (gr < NND) ? fmaf(v.x, g_ac[gk + 0], g_ac[KTOT + gk + 0]) : 0.f; \
            float f1 = (gr < NND) ? fmaf(v.y, g_ac[gk + 1], g_ac[KTOT + gk + 1]) : 0.f; \
            float f2 = (gr < NND) ? fmaf(v.z, g_ac[gk + 2], g_ac[KTOT + gk + 2]) : 0.f; \
            float f3 = (gr < NND) ? fmaf(v.w, g_ac[gk + 3], g_ac[KTOT + gk + 3]) : 0.f; \
            As_[row * 12 + wq * 2 + 0] = pack_h2(f0, f1); \
            As_[row * 12 + wq * 2 + 1] = pack_h2(f2, f3); \
        } \
    } else { \
        const __half* Ah = (const __half*)Ain; \
        int row = tid >> 1, kq = tid & 1; \
        int gr = bm + row, gk = k0_ + kq * 8; \
        int vld = (gr < NND && gk + 8 <= KTOT) ? 16 : 0; \
        const __half* src = vld ? (Ah + (size_t)gr * KTOT + gk) : Ah; \
        cp_async16(aAdr_ + (uint32_t)(row * 12 + kq * 4) * 4, src, vld); \
    } \
    _Pragma("unroll") \
    for (int j = tid; j < BN * 2; j += 256) { \
        int row = j >> 1, kq = j & 1; \
        int gn = bn + row; \
        int vld = (gn < NW) ? 16 : 0; \
        const __half* src = vld ? (WH + (size_t)gn * KPAD + k0_ + kq * 8) : WH; \
        cp_async16(bAdr_ + (uint32_t)(row * 12 + kq * 4) * 4, src, vld); \
    } \
    asm volatile("cp.async.commit_group;" ::: "memory"); \
} while (0)

    STAGE(0, 0);
    for (int c = 0; c < NCH; c++) {
        if (c + 1 < NCH) {
            STAGE(c + 1, (c + 1) & 1);
            asm volatile("cp.async.wait_group 1;" ::: "memory");
        } else {
            asm volatile("cp.async.wait_group 0;" ::: "memory");
        }
        __syncthreads();
        const uint32_t* As = sbuf[c & 1];
        const uint32_t* Bs = sbuf[c & 1] + AW;
        uint32_t af[2][4], bf[WNT][2];
        #pragma unroll
        for (int mt = 0; mt < 2; mt++) {
            int r0 = (warp_m * 32 + mt * 16 + g) * 12;
            af[mt][0] = As[r0 + tig];
            af[mt][1] = As[r0 + 96 + tig];
            af[mt][2] = As[r0 + tig + 4];
            af[mt][3] = As[r0 + 96 + tig + 4];
        }
        #pragma unroll
        for (int nt = 0; nt < WNT; nt++) {
            int cc = (warp_n * (WNT * 8) + nt * 8 + g) * 12;
            bf[nt][0] = Bs[cc + tig];
            bf[nt][1] = Bs[cc + tig + 4];
        }
        #pragma unroll
        for (int mt = 0; mt < 2; mt++)
            #pragma unroll
            for (int nt = 0; nt < WNT; nt++)
                mma_f16(acc[mt][nt], af[mt], bf[nt]);
        __syncthreads();
    }
#undef STAGE

    // ---- epilogue ----
    if (FINAL) {
        #pragma unroll
        for (int mt = 0; mt < 2; mt++) {
            #pragma unroll
            for (int h = 0; h < 2; h++) {
                int r = bm + warp_m * 32 + mt * 16 + g + h * 8;
                float part = 0.f;
                #pragma unroll
                for (int nt = 0; nt < WNT; nt++) {
                    int c0 = bn + warp_n * (WNT * 8) + nt * 8 + tig * 2;
                    if (c0 < NN) {
                        float v0 = fmaxf(acc[mt][nt][h * 2 + 0] + __ldg(bias + c0), 0.f);
                        float v1 = fmaxf(acc[mt][nt][h * 2 + 1] + __ldg(bias + c0 + 1), 0.f);
                        part += v0 * __ldg(w4 + c0) + v1 * __ldg(w4 + c0 + 1);
                    }
                }
                part += __shfl_xor_sync(0xffffffffu, part, 1);
                part += __shfl_xor_sync(0xffffffffu, part, 2);
                if (tig == 0 && r < NND) {
                    if (blockIdx.y == 0) part += __ldg(b4);
                    atomicAdd(&y[__ldg(mol + r)], part);
                }
            }
        }
        return;
    }
    #pragma unroll
    for (int mt = 0; mt < 2; mt++) {
        #pragma unroll
        for (int nt = 0; nt < WNT; nt++) {
            int r0 = bm + warp_m * 32 + mt * 16 + g;
            int c0 = bn + warp_n * (WNT * 8) + nt * 8 + tig * 2;
            float* d = acc[mt][nt];
            #pragma unroll
            for (int h = 0; h < 2; h++) {
                int r = r0 + h * 8;
                if (r < NND && c0 < NN) {
                    float v0 = d[h * 2 + 0] + __ldg(bias + c0);
                    float v1 = d[h * 2 + 1] + __ldg(bias + c0 + 1);
                    if (RELU) { v0 = fmaxf(v0, 0.f); v1 = fmaxf(v1, 0.f); }
                    if (RESID) {
                        float2 xo = *(float2*)&g_x[r * EDIM + c0];
                        float2 xn = {xo.x + 0.1f * v0, xo.y + 0.1f * v1};
                        *(float2*)&g_x[r * EDIM + c0] = xn;
                        *(float2*)&g_xall[r * RDIM + xall_off + c0] = xn;
                    } else {
                        __half2 hv = __floats2half2_rn(v0, v1);
                        *(__half2*)&out[(size_t)r * NN + c0] = hv;
                    }
                }
            }
        }
    }
}

// ---------------- launch ----------------
extern "C" void kernel_launch(void* const* d_in, const int* in_sizes, int n_in,
                              void* d_out, int out_size) {
    const int*   z     = (const int*)d_in[0];
    const int*   eidx  = (const int*)d_in[1];
    const float* dist  = (const float*)d_in[2];
    const int*   mol   = (const int*)d_in[3];
    const float* emb   = (const float*)d_in[4];
    const float* up_bn_g = (const float*)d_in[5];
    const float* up_bn_b = (const float*)d_in[6];
    const float* up_w1 = (const float*)d_in[7];
    const float* up_b1 = (const float*)d_in[8];
    const float* up_w2 = (const float*)d_in[9];
    const float* up_b2 = (const float*)d_in[10];
    const float* up_w3 = (const float*)d_in[11];
    const float* up_b3 = (const float*)d_in[12];
    const float* up_w4 = (const float*)d_in[13];
    const float* up_b4 = (const float*)d_in[14];
    const float* ro_bn_g = (const float*)d_in[15];
    const float* ro_bn_b = (const float*)d_in[16];
    const float* ro_w1 = (const float*)d_in[17];
    const float* ro_b1 = (const float*)d_in[18];
    const float* ro_w2 = (const float*)d_in[19];
    const float* ro_b2 = (const float*)d_in[20];
    const float* ro_w3 = (const float*)d_in[21];
    const float* ro_b3 = (const float*)d_in[22];
    const float* ro_w4 = (const float*)d_in[23];
    const float* ro_b4 = (const float*)d_in[24];
    float* y = (float*)d_out;

    float *pxall;
    __half *ph1, *ph2, *pwH;
    cudaGetSymbolAddress((void**)&ph1, g_h1);
    cudaGetSymbolAddress((void**)&ph2, g_h2);
    cudaGetSymbolAddress((void**)&pxall, g_xall);
    cudaGetSymbolAddress((void**)&pwH, g_wH);

    init_zero<<<NB_SCAN, 256>>>(y);
    embed_kernel<<<(NND * EDIM + 255) / 256, 256>>>(z, emb);

    // all weight transposes -> n-major fp16 (one kernel)
    transpose_all<<<232, 256>>>(up_w1, up_w2, up_w3, up_w4, ro_w1, ro_w2, ro_w3, pwH);

    // CSR build
    csr_count<<<(NE + 255) / 256, 256>>>(eidx);
    scan_local<<<NB_SCAN, 256>>>();
    scan_add<<<(NND + 255) / 256, 256>>>();
    csr_fill<<<(NE + 255) / 256, 256>>>(eidx, eidx + NE, dist);

    // one-time rbf gather + pass-invariant stats (persistent slots)
    gather_rbf<<<(NND + 255) / 256, 256>>>();
    stats_rbf<<<296, 256>>>();

    const int GB = (NND + 127) / 128;   // 391
    dim3 gH(GB, 2), gE(GB, 1);          // 128-wide tiles for N=200; 64-wide for N=64

    for (int t = 0; t < 3; t++) {
        gather_x<<<(NND * 32 + 255) / 256, 256>>>();
        stats_mx_fin<<<296, 256>>>(up_bn_g + t * MDIM, up_bn_b + t * MDIM);
        gemm_f16<MDIM, 6, HH, HH, 8, true, false, false, true, false><<<gH, 256>>>(
            nullptr, pwH + WH_UP1 + t * HH * 96, up_b1 + t * HH, ph1, 0,
            nullptr, nullptr, nullptr, nullptr);
        gemm_f16<HH, 13, HH, HH, 8, true, false, false, false, false><<<gH, 256>>>(
            ph1, pwH + WH_UP2 + t * HH * 208, up_b2 + t * HH, ph2, 0,
            nullptr, nullptr, nullptr, nullptr);
        gemm_f16<HH, 13, HH, HH, 8, true, false, false, false, false><<<gH, 256>>>(
            ph2, pwH + WH_UP3 + t * HH * 208, up_b3 + t * HH, ph1, 0,
            nullptr, nullptr, nullptr, nullptr);
        gemm_f16<HH, 13, EDIM, EDIM, 4, false, false, true, false, false><<<gE, 256>>>(
            ph1, pwH + WH_UP4 + t * EDIM * 208, up_b4 + t * EDIM, nullptr, EDIM * (t + 1),
            nullptr, nullptr, nullptr, nullptr);
    }

    stats_ro_fin<<<296, 256>>>(ro_bn_g, ro_bn_b);
    gemm_f16<RDIM, 16, HH, HH, 8, true, true, false, false, false><<<gH, 256>>>(
        pxall, pwH + WH_RO1, ro_b1, ph1, 0, nullptr, nullptr, nullptr, nullptr);
    gemm_f16<HH, 13, HH, HH, 8, true, false, false, false, false><<<gH, 256>>>(
        ph1, pwH + WH_RO2, ro_b2, ph2, 0, nullptr, nullptr, nullptr, nullptr);
    // final layer: relu(h2 @ w3 + b3) fused with (· w4 + b4) and molecule scatter
    gemm_f16<HH, 13, HH, HH, 8, true, false, false, false, true><<<gH, 256>>>(
        ph2, pwH + WH_RO3, ro_b3, nullptr, 0, ro_w4, ro_b4, mol, y);
}

// round 17
// speedup vs baseline: 1.4511x; 1.0446x over previous
#include <cuda_runtime.h>
#include <cuda_fp16.h>
#include <cstdint>

#define NND 50000
#define NE  800000
#define EDIM 64
#define NS  23
#define MDIM 87
#define HH  200
#define RDIM 256
#define NMOLS 2048
#define NB_SCAN 196   // ceil(NND/256)

// ---------------- scratch (device globals; no allocations) ----------------
__device__ float  g_x[NND * EDIM];
__device__ float  g_xall[NND * RDIM];
__device__ float  g_mrbf[NND * 24];
__device__ float  g_mx[NND * EDIM];
__device__ __half g_h1[NND * HH];
__device__ __half g_h2[NND * HH];
// stats layout: [0..23) rbf sum (persistent), [23..87) mx sum (self-clean),
//               [87..110) rbf sumsq (persistent), [110..174) mx sumsq (self-clean),
//               [512..768) ro sum (self-clean), [768..1024) ro sumsq (self-clean)
__device__ float  g_stats[1024];
__device__ float  g_ac[2 * RDIM];
__device__ int    g_tick_mx;
__device__ int    g_tick_ro;
__device__ int    g_tick_scan;
__device__ __half g_wH[520000];         // n-major [NW][KPAD] fp16 weights
// CSR scratch
__device__ int   g_cnt[NND];
__device__ int   g_excl[NND];
__device__ int   g_bsum[256];
__device__ int   g_boff[256];
__device__ int   g_row[NND + 1];
__device__ int   g_pos[NND];
__device__ int   g_esnk_s[NE];
__device__ float g_edist_s[NE];

// wH offsets (halves), KPAD = 96 / 224 / 256
#define WH_UP1 0        // 3 x 200x96
#define WH_UP2 57600    // 3 x 200x224
#define WH_UP3 192000   // 3 x 200x224
#define WH_UP4 326400   // 3 x 64x224
#define WH_RO1 369408   // 200x256
#define WH_RO2 420608   // 200x224
#define WH_RO3 465408   // 200x224

// ---------------- helpers ----------------
__device__ __forceinline__ uint32_t smem_u32(const void* p) {
    uint32_t a;
    asm("{ .reg .u64 t; cvta.to.shared.u64 t, %1; cvt.u32.u64 %0, t; }" : "=r"(a) : "l"(p));
    return a;
}
__device__ __forceinline__ void cp_async16(uint32_t dst, const void* src, int valid) {
    asm volatile("cp.async.cg.shared.global [%0], [%1], 16, %2;"
                 :: "r"(dst), "l"(src), "r"(valid) : "memory");
}
__device__ __forceinline__ void mma_f16(float* d, const uint32_t* a, const uint32_t* b) {
    asm volatile(
        "mma.sync.aligned.m16n8k16.row.col.f32.f16.f16.f32 "
        "{%0,%1,%2,%3}, {%4,%5,%6,%7}, {%8,%9}, {%0,%1,%2,%3};"
        : "+f"(d[0]), "+f"(d[1]), "+f"(d[2]), "+f"(d[3])
        : "r"(a[0]), "r"(a[1]), "r"(a[2]), "r"(a[3]), "r"(b[0]), "r"(b[1]));
}
__device__ __forceinline__ uint32_t pack_h2(float a, float b) {
    __half2 h = __floats2half2_rn(a, b);
    return *(uint32_t*)&h;
}

// ---------------- init / utility ----------------
__global__ void init_zero(float* __restrict__ y) {
    int i = blockIdx.x * blockDim.x + threadIdx.x;
    if (i < NMOLS) y[i] = 0.f;
    if (i < NND) g_cnt[i] = 0;
    if (blockIdx.x == 0 && threadIdx.x < NS) {
        g_stats[threadIdx.x] = 0.f;
        g_stats[MDIM + threadIdx.x] = 0.f;
    }
}
__global__ void embed_kernel(const int* __restrict__ z, const float* __restrict__ emb) {
    int i = blockIdx.x * blockDim.x + threadIdx.x;
    if (i >= NND * EDIM) return;
    int n = i >> 6, d = i & 63;
    float v = emb[(z[n] << 6) + d];
    g_x[i] = v;
    g_xall[(n << 8) + d] = v;
}

// all 7 weight transposes fused: in [nt][K][NW] float -> wH[off + [nt][NW][KPAD]] half
__global__ void transpose_all(const float* __restrict__ w1, const float* __restrict__ w2,
                              const float* __restrict__ w3, const float* __restrict__ w4,
                              const float* __restrict__ r1, const float* __restrict__ r2,
                              const float* __restrict__ r3, __half* __restrict__ out) {
    int gid = blockIdx.x * blockDim.x + threadIdx.x;
    int stride = gridDim.x * blockDim.x;
    auto doReg = [&](const float* __restrict__ in, int K, int NW, int KPAD, int off, int total) {
        int per = NW * KPAD;
        for (int i = gid; i < total; i += stride) {
            int t = i / per, rem = i - t * per;
            int n = rem / KPAD, k = rem - n * KPAD;
            float v = (k < K) ? in[(size_t)t * K * NW + (size_t)k * NW + n] : 0.f;
            out[off + i] = __float2half(v);
        }
    };
    doReg(w1, MDIM, HH,   96, WH_UP1, 57600);
    doReg(w2, HH,   HH,  224, WH_UP2, 134400);
    doReg(w3, HH,   HH,  224, WH_UP3, 134400);
    doReg(w4, HH,  EDIM, 224, WH_UP4, 43008);
    doReg(r1, RDIM, HH,  256, WH_RO1, 51200);
    doReg(r2, HH,   HH,  224, WH_RO2, 44800);
    doReg(r3, HH,   HH,  224, WH_RO3, 44800);
}

// ---------------- CSR build ----------------
__global__ void csr_count(const int* __restrict__ esrc) {
    int e = blockIdx.x * blockDim.x + threadIdx.x;
    if (e < NE) atomicAdd(&g_cnt[esrc[e]], 1);
}
// local scan; last block also scans the block sums into g_boff (ticket pattern)
__global__ void scan_local() {
    __shared__ int sh[256];
    __shared__ int lastf;
    int i = blockIdx.x * 256 + threadIdx.x;
    int v = (i < NND) ? g_cnt[i] : 0;
    sh[threadIdx.x] = v;
    __syncthreads();
    #pragma unroll
    for (int off = 1; off < 256; off <<= 1) {
        int t = (threadIdx.x >= off) ? sh[threadIdx.x - off] : 0;
        __syncthreads();
        sh[threadIdx.x] += t;
        __syncthreads();
    }
    if (i < NND) g_excl[i] = sh[threadIdx.x] - v;
    if (threadIdx.x == 255) g_bsum[blockIdx.x] = sh[255];
    __syncthreads();
    if (threadIdx.x == 0) {
        __threadfence();
        lastf = (atomicAdd(&g_tick_scan, 1) == (int)gridDim.x - 1);
    }
    __syncthreads();
    if (lastf) {
        int b = (threadIdx.x < NB_SCAN) ? g_bsum[threadIdx.x] : 0;
        sh[threadIdx.x] = b;
        __syncthreads();
        #pragma unroll
        for (int off = 1; off < 256; off <<= 1) {
            int t = (threadIdx.x >= off) ? sh[threadIdx.x - off] : 0;
            __syncthreads();
            sh[threadIdx.x] += t;
            __syncthreads();
        }
        g_boff[threadIdx.x] = sh[threadIdx.x] - b;
        if (threadIdx.x == 0) g_tick_scan = 0;
    }
}
__global__ void scan_add() {
    int i = blockIdx.x * blockDim.x + threadIdx.x;
    if (i < NND) {
        int r = g_excl[i] + g_boff[i >> 8];
        g_row[i] = r;
        g_pos[i] = r;
    }
    if (i == 0) g_row[NND] = NE;
}
__global__ void csr_fill(const int* __restrict__ esrc, const int* __restrict__ esnk,
                         const float* __restrict__ dist) {
    int e = blockIdx.x * blockDim.x + threadIdx.x;
    if (e >= NE) return;
    int p = atomicAdd(&g_pos[esrc[e]], 1);
    g_esnk_s[p] = esnk[e];
    g_edist_s[p] = dist[e];
}

// ---------------- gathers ----------------
__global__ void gather_x() {
    int gt = blockIdx.x * blockDim.x + threadIdx.x;
    int node = gt >> 5, lane = gt & 31;
    if (node >= NND) return;
    int s = g_row[node], e = g_row[node + 1];
    float a0 = 0.f, a1 = 0.f;
    for (int i = s; i < e; i++) {
        int snk = g_esnk_s[i] << 6;
        a0 += g_x[snk + lane];
        a1 += g_x[snk + 32 + lane];
    }
    g_mx[(node << 6) + lane] = a0;
    g_mx[(node << 6) + 32 + lane] = a1;
}
__global__ void gather_rbf() {
    int node = blockIdx.x * blockDim.x + threadIdx.x;
    if (node >= NND) return;
    int s = g_row[node], e = g_row[node + 1];
    float acc[NS];
    #pragma unroll
    for (int f = 0; f < NS; f++) acc[f] = 0.f;
    for (int i = s; i < e; i++) {
        float t = g_edist_s[i] - 0.8f;
        float v = __expf(-t * t);
        float u = __expf(0.2f * t);
        float r = u * 0.99004983f;
        acc[0] += v;
        #pragma unroll
        for (int f = 1; f < NS; f++) {
            v *= r;
            acc[f] += v;
            r *= 0.98019867f;
        }
    }
    #pragma unroll
    for (int f = 0; f < NS; f++) g_mrbf[node * 24 + f] = acc[f];
}

// ---------------- batchnorm stats (self-cleaning, fused finalize) ----------------
__global__ void stats_rbf() {
    __shared__ float ss[24], sq[24];
    if (threadIdx.x < 24) { ss[threadIdx.x] = 0.f; sq[threadIdx.x] = 0.f; }
    __syncthreads();
    int stride = gridDim.x * blockDim.x;
    for (int idx = blockIdx.x * blockDim.x + threadIdx.x; idx < NND * 24; idx += stride) {
        int c = idx % 24;
        if (c < NS) {
            float v = g_mrbf[idx];
            atomicAdd(&ss[c], v);
            atomicAdd(&sq[c], v * v);
        }
    }
    __syncthreads();
    if (threadIdx.x < NS) {
        atomicAdd(&g_stats[threadIdx.x], ss[threadIdx.x]);
        atomicAdd(&g_stats[MDIM + threadIdx.x], sq[threadIdx.x]);
    }
}

// mx stats over g_mx; last block computes full MDIM g_ac and self-cleans.
__global__ void stats_mx_fin(const float* __restrict__ bng, const float* __restrict__ bnb) {
    int tid = threadIdx.x;
    float s = 0.f, q = 0.f;
    int stride = gridDim.x * 256;
    for (int idx = blockIdx.x * 256 + tid; idx < NND * EDIM; idx += stride) {
        float v = g_mx[idx];
        s += v; q += v * v;
    }
    __shared__ float sh[512];
    __shared__ int lastf;
    sh[tid] = s; sh[256 + tid] = q;
    __syncthreads();
    if (tid < 64) {
        float S = 0.f, Q = 0.f;
        #pragma unroll
        for (int j = tid; j < 256; j += 64) { S += sh[j]; Q += sh[256 + j]; }
        atomicAdd(&g_stats[NS + tid], S);
        atomicAdd(&g_stats[MDIM + NS + tid], Q);
        __threadfence();
    }
    __syncthreads();
    if (tid == 0) lastf = (atomicAdd(&g_tick_mx, 1) == (int)gridDim.x - 1);
    __syncthreads();
    if (lastf) {
        if (tid < MDIM) {
            const float inv = 1.f / (float)NND;
            float mean = g_stats[tid] * inv;
            float var = fmaxf(g_stats[MDIM + tid] * inv - mean * mean, 0.f);
            float a = bng[tid] * rsqrtf(var + 1e-5f);
            g_ac[tid] = a;
            g_ac[MDIM + tid] = bnb[tid] - mean * a;
        }
        __syncthreads();
        if (tid < 64) { g_stats[NS + tid] = 0.f; g_stats[MDIM + NS + tid] = 0.f; }
        if (tid == 0) g_tick_mx = 0;
    }
}

// readout stats over g_xall; last block computes RDIM g_ac and self-cleans.
__global__ void stats_ro_fin(const float* __restrict__ bng, const float* __restrict__ bnb) {
    int tid = threadIdx.x;
    float s = 0.f, q = 0.f;
    int stride = gridDim.x * 256;
    for (int idx = blockIdx.x * 256 + tid; idx < NND * RDIM; idx += stride) {
        float v = g_xall[idx];
        s += v; q += v * v;
    }
    __shared__ int lastf;
    atomicAdd(&g_stats[512 + tid], s);
    atomicAdd(&g_stats[768 + tid], q);
    __threadfence();
    __syncthreads();
    if (tid == 0) lastf = (atomicAdd(&g_tick_ro, 1) == (int)gridDim.x - 1);
    __syncthreads();
    if (lastf) {
        const float inv = 1.f / (float)NND;
        float mean = g_stats[512 + tid] * inv;
        float var = fmaxf(g_stats[768 + tid] * inv - mean * mean, 0.f);
        float a = bng[tid] * rsqrtf(var + 1e-5f);
        g_ac[tid] = a;
        g_ac[RDIM + tid] = bnb[tid] - mean * a;
        g_stats[512 + tid] = 0.f;
        g_stats[768 + tid] = 0.f;
        if (tid == 0) g_tick_ro = 0;
    }
}

// ---------------- fp16 m16n8k16 double-buffered GEMM, BK=32 chunks ------------
// BN = WNT*16. 8 warps as 4(m) x 2(n). A stage [row][16w] stride 20; B same.
// D[128 x NN] = epi(A' @ WH^T + bias). WH: [NW][KPAD] n-major half, KPAD=NCH*32.
// Paths: SPLITA (mrbf+mx, BN fold), BNIN (fp32 A, BN fold), else cp.async half A.
// RESID: g_x += 0.1*D (fp32) + g_xall slice.
// FINAL: relu then dot with w4, atomicAdd into y[mol[row]] (b4 from y-block 0 only).
template <int KTOT, int NCH, int NN, int NW, int WNT, bool RELU, bool BNIN, bool RESID,
          bool SPLITA, bool FINAL>
__global__ __launch_bounds__(256, 2)
void gemm_f16(const void* __restrict__ Ain, const __half* __restrict__ WH,
              const float* __restrict__ bias, __half* __restrict__ out, int xall_off,
              const float* __restrict__ w4, const float* __restrict__ b4,
              const int* __restrict__ mol, float* __restrict__ y) {
    constexpr int KPAD = NCH * 32;
    constexpr int BN = WNT * 16;
    constexpr int AW = 128 * 20;   // A stage words ([row][16 half2 words], stride 20)
    constexpr int BW = BN * 20;    // B stage words
    __shared__ __align__(16) uint32_t sbuf[2][AW + BW];

    int tid = threadIdx.x, lane = tid & 31, wid = tid >> 5;
    int warp_m = wid & 3, warp_n = wid >> 2;
    int g = lane >> 2, tig = lane & 3;
    int bm = blockIdx.x * 128, bn = blockIdx.y * BN;
    uint32_t sbase = smem_u32(sbuf);

    float acc[2][WNT][4] = {};

#define STAGE(cc, bb) do { \
    int k0_ = (cc) * 32; \
    uint32_t* As_ = sbuf[bb]; \
    uint32_t aAdr_ = sbase + (uint32_t)(bb) * (AW + BW) * 4; \
    uint32_t bAdr_ = aAdr_ + AW * 4; \
    if (SPLITA) { \
        _Pragma("unroll") \
        for (int j = 0; j < 8; j++) { \
            int idx = tid + j * 256; \
            int row = idx >> 4, w = idx & 15; \
            int gr = bm + row, gk = k0_ + 2 * w; \
            float v0 = 0.f, v1 = 0.f; \
            if (gr < NND) { \
                if (gk < KTOT) { \
                    v0 = (gk < NS) ? g_mrbf[gr * 24 + gk] : g_mx[gr * 64 + gk - NS]; \
                    v0 = fmaf(v0, g_ac[gk], g_ac[KTOT + gk]); \
                } \
                if (gk + 1 < KTOT) { \
                    v1 = (gk + 1 < NS) ? g_mrbf[gr * 24 + gk + 1] : g_mx[gr * 64 + gk + 1 - NS]; \
                    v1 = fmaf(v1, g_ac[gk + 1], g_ac[KTOT + gk + 1]); \
                } \
            } \
            As_[row * 20 + w] = pack_h2(v0, v1); \
        } \
    } else if (BNIN) { \
        const float* Af = (const float*)Ain; \
        _Pragma("unroll") \
        for (int j = 0; j < 4; j++) { \
            int idx = tid + j * 256; \
            int row = idx >> 3, wq = idx & 7; \
            int gr = bm + row, gk = k0_ + wq * 4; \
            float4 v = {0.f, 0.f, 0.f, 0.f}; \
            if (gr < NND && gk + 4 <= KTOT) v = *(const float4*)(Af + (size_t)gr * KTOT + gk); \
            float f0 = (gr < NND) ? fmaf(v.x, g_ac[gk + 0], g_ac[KTOT + gk + 0]) : 0.f; \
            float f1 = (gr < NND) ? fmaf(v.y, g_ac[gk + 1], g_ac[KTOT + gk + 1]) : 0.f; \
            float f2 = (gr < NND) ? fmaf(v.z, g_ac[gk + 2], g_ac[KTOT + gk + 2]) : 0.f; \
            float f3 = (gr < NND) ? fmaf(v.w, g_ac[gk + 3], g_ac[KTOT + gk + 3]) : 0.f; \
            As_[row * 20 + wq * 2 + 0] = pack_h2(f0, f1); \
            As_[row * 20 + wq * 2 + 1] = pack_h2(f2, f3); \
        } \
    } else { \
        const __half* Ah = (const __half*)Ain; \
        _Pragma("unroll") \
        for (int j = 0; j < 2; j++) { \
            int idx = tid + j * 256; \
            int row = idx >> 2, kq = idx & 3; \
            int gr = bm + row, gk = k0_ + kq * 8; \
            int vld = (gr < NND && gk + 8 <= KTOT) ? 16 : 0; \
            const __half* src = vld ? (Ah + (size_t)gr * KTOT + gk) : Ah; \
            cp_async16(aAdr_ + (uint32_t)(row * 20 + kq * 4) * 4, src, vld); \
        } \
    } \
    _Pragma("unroll") \
    for (int j = tid; j < BN * 4; j += 256) { \
        int row = j >> 2, kq = j & 3; \
        int gn = bn + row; \
        int vld = (gn < NW) ? 16 : 0; \
        const __half* src = vld ? (WH + (size_t)gn * KPAD + k0_ + kq * 8) : WH; \
        cp_async16(bAdr_ + (uint32_t)(row * 20 + kq * 4) * 4, src, vld); \
    } \
    asm volatile("cp.async.commit_group;" ::: "memory"); \
} while (0)

    STAGE(0, 0);
    for (int c = 0; c < NCH; c++) {
        if (c + 1 < NCH) {
            STAGE(c + 1, (c + 1) & 1);
            asm volatile("cp.async.wait_group 1;" ::: "memory");
        } else {
            asm volatile("cp.async.wait_group 0;" ::: "memory");
        }
        __syncthreads();
        const uint32_t* As = sbuf[c & 1];
        const uint32_t* Bs = sbuf[c & 1] + AW;
        #pragma unroll
        for (int ks = 0; ks < 2; ks++) {
            int kb = ks * 8;
            uint32_t af[2][4], bf[WNT][2];
            #pragma unroll
            for (int mt = 0; mt < 2; mt++) {
                int r0 = (warp_m * 32 + mt * 16 + g) * 20;
                af[mt][0] = As[r0 + kb + tig];
                af[mt][1] = As[r0 + 160 + kb + tig];
                af[mt][2] = As[r0 + kb + tig + 4];
                af[mt][3] = As[r0 + 160 + kb + tig + 4];
            }
            #pragma unroll
            for (int nt = 0; nt < WNT; nt++) {
                int cc = (warp_n * (WNT * 8) + nt * 8 + g) * 20;
                bf[nt][0] = Bs[cc + kb + tig];
                bf[nt][1] = Bs[cc + kb + tig + 4];
            }
            #pragma unroll
            for (int mt = 0; mt < 2; mt++)
                #pragma unroll
                for (int nt = 0; nt < WNT; nt++)
                    mma_f16(acc[mt][nt], af[mt], bf[nt]);
        }
        __syncthreads();
    }
#undef STAGE

    // ---- epilogue ----
    if (FINAL) {
        #pragma unroll
        for (int mt = 0; mt < 2; mt++) {
            #pragma unroll
            for (int h = 0; h < 2; h++) {
                int r = bm + warp_m * 32 + mt * 16 + g + h * 8;
                float part = 0.f;
                #pragma unroll
                for (int nt = 0; nt < WNT; nt++) {
                    int c0 = bn + warp_n * (WNT * 8) + nt * 8 + tig * 2;
                    if (c0 < NN) {
                        float v0 = fmaxf(acc[mt][nt][h * 2 + 0] + __ldg(bias + c0), 0.f);
                        float v1 = fmaxf(acc[mt][nt][h * 2 + 1] + __ldg(bias + c0 + 1), 0.f);
                        part += v0 * __ldg(w4 + c0) + v1 * __ldg(w4 + c0 + 1);
                    }
                }
                part += __shfl_xor_sync(0xffffffffu, part, 1);
                part += __shfl_xor_sync(0xffffffffu, part, 2);
                if (tig == 0 && r < NND) {
                    if (blockIdx.y == 0) part += __ldg(b4);
                    atomicAdd(&y[__ldg(mol + r)], part);
                }
            }
        }
        return;
    }
    #pragma unroll
    for (int mt = 0; mt < 2; mt++) {
        #pragma unroll
        for (int nt = 0; nt < WNT; nt++) {
            int r0 = bm + warp_m * 32 + mt * 16 + g;
            int c0 = bn + warp_n * (WNT * 8) + nt * 8 + tig * 2;
            float* d = acc[mt][nt];
            #pragma unroll
            for (int h = 0; h < 2; h++) {
                int r = r0 + h * 8;
                if (r < NND && c0 < NN) {
                    float v0 = d[h * 2 + 0] + __ldg(bias + c0);
                    float v1 = d[h * 2 + 1] + __ldg(bias + c0 + 1);
                    if (RELU) { v0 = fmaxf(v0, 0.f); v1 = fmaxf(v1, 0.f); }
                    if (RESID) {
                        float2 xo = *(float2*)&g_x[r * EDIM + c0];
                        float2 xn = {xo.x + 0.1f * v0, xo.y + 0.1f * v1};
                        *(float2*)&g_x[r * EDIM + c0] = xn;
                        *(float2*)&g_xall[r * RDIM + xall_off + c0] = xn;
                    } else {
                        __half2 hv = __floats2half2_rn(v0, v1);
                        *(__half2*)&out[(size_t)r * NN + c0] = hv;
                    }
                }
            }
        }
    }
}

// ---------------- launch ----------------
extern "C" void kernel_launch(void* const* d_in, const int* in_sizes, int n_in,
                              void* d_out, int out_size) {
    const int*   z     = (const int*)d_in[0];
    const int*   eidx  = (const int*)d_in[1];
    const float* dist  = (const float*)d_in[2];
    const int*   mol   = (const int*)d_in[3];
    const float* emb   = (const float*)d_in[4];
    const float* up_bn_g = (const float*)d_in[5];
    const float* up_bn_b = (const float*)d_in[6];
    const float* up_w1 = (const float*)d_in[7];
    const float* up_b1 = (const float*)d_in[8];
    const float* up_w2 = (const float*)d_in[9];
    const float* up_b2 = (const float*)d_in[10];
    const float* up_w3 = (const float*)d_in[11];
    const float* up_b3 = (const float*)d_in[12];
    const float* up_w4 = (const float*)d_in[13];
    const float* up_b4 = (const float*)d_in[14];
    const float* ro_bn_g = (const float*)d_in[15];
    const float* ro_bn_b = (const float*)d_in[16];
    const float* ro_w1 = (const float*)d_in[17];
    const float* ro_b1 = (const float*)d_in[18];
    const float* ro_w2 = (const float*)d_in[19];
    const float* ro_b2 = (const float*)d_in[20];
    const float* ro_w3 = (const float*)d_in[21];
    const float* ro_b3 = (const float*)d_in[22];
    const float* ro_w4 = (const float*)d_in[23];
    const float* ro_b4 = (const float*)d_in[24];
    float* y = (float*)d_out;

    float *pxall;
    __half *ph1, *ph2, *pwH;
    cudaGetSymbolAddress((void**)&ph1, g_h1);
    cudaGetSymbolAddress((void**)&ph2, g_h2);
    cudaGetSymbolAddress((void**)&pxall, g_xall);
    cudaGetSymbolAddress((void**)&pwH, g_wH);

    init_zero<<<NB_SCAN, 256>>>(y);
    embed_kernel<<<(NND * EDIM + 255) / 256, 256>>>(z, emb);

    // all weight transposes -> n-major fp16 (one kernel)
    transpose_all<<<232, 256>>>(up_w1, up_w2, up_w3, up_w4, ro_w1, ro_w2, ro_w3, pwH);

    // CSR build
    csr_count<<<(NE + 255) / 256, 256>>>(eidx);
    scan_local<<<NB_SCAN, 256>>>();
    scan_add<<<(NND + 255) / 256, 256>>>();
    csr_fill<<<(NE + 255) / 256, 256>>>(eidx, eidx + NE, dist);

    // one-time rbf gather + pass-invariant stats (persistent slots)
    gather_rbf<<<(NND + 255) / 256, 256>>>();
    stats_rbf<<<296, 256>>>();

    const int GB = (NND + 127) / 128;   // 391
    dim3 gH(GB, 2), gE(GB, 1);          // 128-wide tiles for N=200; 64-wide for N=64

    for (int t = 0; t < 3; t++) {
        gather_x<<<(NND * 32 + 255) / 256, 256>>>();
        stats_mx_fin<<<296, 256>>>(up_bn_g + t * MDIM, up_bn_b + t * MDIM);
        gemm_f16<MDIM, 3, HH, HH, 8, true, false, false, true, false><<<gH, 256>>>(
            nullptr, pwH + WH_UP1 + t * HH * 96, up_b1 + t * HH, ph1, 0,
            nullptr, nullptr, nullptr, nullptr);
        gemm_f16<HH, 7, HH, HH, 8, true, false, false, false, false><<<gH, 256>>>(
            ph1, pwH + WH_UP2 + t * HH * 224, up_b2 + t * HH, ph2, 0,
            nullptr, nullptr, nullptr, nullptr);
        gemm_f16<HH, 7, HH, HH, 8, true, false, false, false, false><<<gH, 256>>>(
            ph2, pwH + WH_UP3 + t * HH * 224, up_b3 + t * HH, ph1, 0,
            nullptr, nullptr, nullptr, nullptr);
        gemm_f16<HH, 7, EDIM, EDIM, 4, false, false, true, false, false><<<gE, 256>>>(
            ph1, pwH + WH_UP4 + t * EDIM * 224, up_b4 + t * EDIM, nullptr, EDIM * (t + 1),
            nullptr, nullptr, nullptr, nullptr);
    }

    stats_ro_fin<<<296, 256>>>(ro_bn_g, ro_bn_b);
    gemm_f16<RDIM, 8, HH, HH, 8, true, true, false, false, false><<<gH, 256>>>(
        pxall, pwH + WH_RO1, ro_b1, ph1, 0, nullptr, nullptr, nullptr, nullptr);
    gemm_f16<HH, 7, HH, HH, 8, true, false, false, false, false><<<gH, 256>>>(
        ph1, pwH + WH_RO2, ro_b2, ph2, 0, nullptr, nullptr, nullptr, nullptr);
    // final layer: relu(h2 @ w3 + b3) fused with (· w4 + b4) and molecule scatter
    gemm_f16<HH, 7, HH, HH, 8, true, false, false, false, true><<<gH, 256>>>(
        ph2, pwH + WH_RO3, ro_b3, nullptr, 0, ro_w4, ro_b4, mol, y);
}